// round 8
// baseline (speedup 1.0000x reference)
#include <cuda_runtime.h>
#include <cuda_bf16.h>
#include <cstdint>

// ---------------------------------------------------------------------------
// RecurrentInhibition collapsed to y = M x (M = A^10 + 0.05*sum A^i), folded
// by centrosymmetry into two 64x64 GEMMs (S = Me u, D = Mo v), executed on
// tensor cores via bf16 hi/lo split (3-term) mma.sync with fp32 accumulate.
// R8: 4 batch-tiles per CTA (single-wave grid), register X prefetch under the
// mma phase, pinned 3 CTAs/SM. (tcgen05 unavailable: harness targets sm_100.)
// ---------------------------------------------------------------------------

#define CCH    128
#define HCH    64
#define SCOPE  27
#define HALF   13
#define NSTEP  10
#define DECAYF 0.05f
#define PSP    3136          // 56*56
#define NB     32
#define NP     64            // spatial tile per CTA
#define NPT    49            // 3136 / 64
#define TILES  4             // batch tiles per CTA
#define PITCH  72            // bf16 row pitch: 144B = 9*16 (aligned), conflict-free
#define NTHR   256

// Folded matrices in bf16 hi/lo, row-major [i][k], i,k in 0..63
__device__ __align__(16) __nv_bfloat16 g_Aehi[HCH * HCH];
__device__ __align__(16) __nv_bfloat16 g_Aelo[HCH * HCH];
__device__ __align__(16) __nv_bfloat16 g_Aohi[HCH * HCH];
__device__ __align__(16) __nv_bfloat16 g_Aolo[HCH * HCH];

// ---------------------------------------------------------------------------
// Precompute: block k computes M[:,k], M[:,127-k] by iterating the recurrence
// on a unit-vector pair, folds to Me/Mo, splits bf16 hi/lo, stores [i][k].
// ---------------------------------------------------------------------------
__global__ void build_M_kernel(const float* __restrict__ w_rec) {
    __shared__ float w[SCOPE];
    __shared__ float2 ybuf[2][CCH];

    const int k = blockIdx.x;    // 0..63
    const int r = threadIdx.x;   // 0..127

    if (r < SCOPE) w[r] = w_rec[r];

    const float2 x0 = make_float2(r == k ? 1.0f : 0.0f,
                                  r == (CCH - 1 - k) ? 1.0f : 0.0f);
    ybuf[0][r] = x0;
    __syncthreads();

    int cur = 0;
    for (int it = 0; it < NSTEP; ++it) {
        float2 acc = make_float2(0.0f, 0.0f);
        #pragma unroll
        for (int t = 0; t < SCOPE; ++t) {
            int j = r + t - HALF;
            if (j >= 0 && j < CCH) {
                float2 yv = ybuf[cur][j];
                acc.x += w[t] * yv.x;
                acc.y += w[t] * yv.y;
            }
        }
        float2 yc = ybuf[cur][r];
        float2 yn;
        yn.x = (1.0f - DECAYF) * yc.x + DECAYF * (x0.x + acc.x);
        yn.y = (1.0f - DECAYF) * yc.y + DECAYF * (x0.y + acc.y);
        ybuf[cur ^ 1][r] = yn;
        __syncthreads();
        cur ^= 1;
    }

    if (r < HCH) {
        float a = ybuf[cur][r].x;          // M[r][k]
        float b = ybuf[cur][r].y;          // M[r][127-k]
        float me = 0.5f * (a + b);
        float mo = 0.5f * (a - b);
        __nv_bfloat16 mehi = __float2bfloat16_rn(me);
        __nv_bfloat16 melo = __float2bfloat16_rn(me - __bfloat162float(mehi));
        __nv_bfloat16 mohi = __float2bfloat16_rn(mo);
        __nv_bfloat16 molo = __float2bfloat16_rn(mo - __bfloat162float(mohi));
        g_Aehi[r * HCH + k] = mehi;
        g_Aelo[r * HCH + k] = melo;
        g_Aohi[r * HCH + k] = mohi;
        g_Aolo[r * HCH + k] = molo;
    }
}

// ---------------------------------------------------------------------------
// PTX helpers (sm_100-safe: mma.sync / ldmatrix / cp.async only)
// ---------------------------------------------------------------------------
__device__ __forceinline__ uint32_t smem_u32(const void* p) {
    uint32_t a;
    asm("{ .reg .u64 t; cvta.to.shared.u64 t, %1; cvt.u32.u64 %0, t; }"
        : "=r"(a) : "l"(p));
    return a;
}
__device__ __forceinline__ void cp_async16(uint32_t dst, const void* src) {
    asm volatile("cp.async.cg.shared.global [%0], [%1], 16;"
                 :: "r"(dst), "l"(src));
}
__device__ __forceinline__ void cp_async_commit() {
    asm volatile("cp.async.commit_group;");
}
__device__ __forceinline__ void cp_async_wait0() {
    asm volatile("cp.async.wait_group 0;");
}
__device__ __forceinline__ void ldsm_x4(uint32_t addr, uint32_t r[4]) {
    asm volatile("ldmatrix.sync.aligned.m8n8.x4.shared.b16 {%0,%1,%2,%3}, [%4];"
                 : "=r"(r[0]), "=r"(r[1]), "=r"(r[2]), "=r"(r[3]) : "r"(addr));
}
__device__ __forceinline__ void ldsm_x4_t(uint32_t addr, uint32_t r[4]) {
    asm volatile("ldmatrix.sync.aligned.m8n8.x4.trans.shared.b16 {%0,%1,%2,%3}, [%4];"
                 : "=r"(r[0]), "=r"(r[1]), "=r"(r[2]), "=r"(r[3]) : "r"(addr));
}
__device__ __forceinline__ void mma_bf16(float d[4], const uint32_t a[4],
                                         uint32_t b0, uint32_t b1) {
    asm volatile(
        "mma.sync.aligned.m16n8k16.row.col.f32.bf16.bf16.f32 "
        "{%0,%1,%2,%3}, {%4,%5,%6,%7}, {%8,%9}, {%0,%1,%2,%3};"
        : "+f"(d[0]), "+f"(d[1]), "+f"(d[2]), "+f"(d[3])
        : "r"(a[0]), "r"(a[1]), "r"(a[2]), "r"(a[3]), "r"(b0), "r"(b1));
}
__device__ __forceinline__ uint32_t pack_bf16(float a, float b) {
    __nv_bfloat162 h = __floats2bfloat162_rn(a, b);   // .x = a (low half)
    return *reinterpret_cast<uint32_t*>(&h);
}

// ---------------------------------------------------------------------------
// Fold registers (xt = x rows c, xm = mirror rows 127-c) into bf16 hi/lo smem.
// ---------------------------------------------------------------------------
__device__ __forceinline__ void fold_store(const float4 xt[4], const float4 xm[4],
                                           int c0, int p4,
                                           __nv_bfloat16* sUh, __nv_bfloat16* sUl,
                                           __nv_bfloat16* sVh, __nv_bfloat16* sVl) {
    #pragma unroll
    for (int it = 0; it < 4; ++it) {
        const int c = c0 + (it << 4);
        float u[4] = {xt[it].x + xm[it].x, xt[it].y + xm[it].y,
                      xt[it].z + xm[it].z, xt[it].w + xm[it].w};
        float v[4] = {xt[it].x - xm[it].x, xt[it].y - xm[it].y,
                      xt[it].z - xm[it].z, xt[it].w - xm[it].w};
        float uh[4], vh[4];
        #pragma unroll
        for (int e = 0; e < 4; ++e) {
            uh[e] = __bfloat162float(__float2bfloat16_rn(u[e]));
            vh[e] = __bfloat162float(__float2bfloat16_rn(v[e]));
        }
        uint2 wuh = make_uint2(pack_bf16(uh[0], uh[1]), pack_bf16(uh[2], uh[3]));
        uint2 wul = make_uint2(pack_bf16(u[0] - uh[0], u[1] - uh[1]),
                               pack_bf16(u[2] - uh[2], u[3] - uh[3]));
        uint2 wvh = make_uint2(pack_bf16(vh[0], vh[1]), pack_bf16(vh[2], vh[3]));
        uint2 wvl = make_uint2(pack_bf16(v[0] - vh[0], v[1] - vh[1]),
                               pack_bf16(v[2] - vh[2], v[3] - vh[3]));
        const int off = c * PITCH + p4;
        *(uint2*)&sUh[off] = wuh;
        *(uint2*)&sUl[off] = wul;
        *(uint2*)&sVh[off] = wvh;
        *(uint2*)&sVl[off] = wvl;
    }
}

// ---------------------------------------------------------------------------
// MMA phase + epilogue for one tile. Per kk: A-ldsm, U-ldsm, S-mmas, V-ldsm,
// D-mmas — S issue overlaps V fragment loads.
// ---------------------------------------------------------------------------
__device__ __forceinline__ void mma_tile(
    const __nv_bfloat16* sAeh, const __nv_bfloat16* sAel,
    const __nv_bfloat16* sAoh, const __nv_bfloat16* sAol,
    const __nv_bfloat16* sUh,  const __nv_bfloat16* sUl,
    const __nv_bfloat16* sVh,  const __nv_bfloat16* sVl,
    int i0, int wn, int lane, float* ob /* out + b*CCH*PSP + p0 */) {

    const int lr = lane & 15;
    const int lc = (lane >> 4) << 3;

    const uint32_t aeh_b = smem_u32(&sAeh[(i0 + lr) * PITCH + lc]);
    const uint32_t ael_b = smem_u32(&sAel[(i0 + lr) * PITCH + lc]);
    const uint32_t aoh_b = smem_u32(&sAoh[(i0 + lr) * PITCH + lc]);
    const uint32_t aol_b = smem_u32(&sAol[(i0 + lr) * PITCH + lc]);
    const uint32_t uh_b0 = smem_u32(&sUh[lr * PITCH + wn + lc]);
    const uint32_t uh_b1 = smem_u32(&sUh[lr * PITCH + wn + 16 + lc]);
    const uint32_t ul_b0 = smem_u32(&sUl[lr * PITCH + wn + lc]);
    const uint32_t ul_b1 = smem_u32(&sUl[lr * PITCH + wn + 16 + lc]);
    const uint32_t vh_b0 = smem_u32(&sVh[lr * PITCH + wn + lc]);
    const uint32_t vh_b1 = smem_u32(&sVh[lr * PITCH + wn + 16 + lc]);
    const uint32_t vl_b0 = smem_u32(&sVl[lr * PITCH + wn + lc]);
    const uint32_t vl_b1 = smem_u32(&sVl[lr * PITCH + wn + 16 + lc]);

    float accS[4][4], accD[4][4];
    #pragma unroll
    for (int j = 0; j < 4; ++j)
        #pragma unroll
        for (int e = 0; e < 4; ++e) { accS[j][e] = 0.0f; accD[j][e] = 0.0f; }

    #pragma unroll
    for (int kk = 0; kk < 4; ++kk) {
        const uint32_t adelta = kk * 32;                 // 16 bf16 along k
        const uint32_t bdelta = kk * 16 * PITCH * 2;     // 16 k-rows

        uint32_t aeh[4], ael[4], aoh[4], aol[4];
        ldsm_x4(aeh_b + adelta, aeh);
        ldsm_x4(ael_b + adelta, ael);
        ldsm_x4(aoh_b + adelta, aoh);
        ldsm_x4(aol_b + adelta, aol);

        uint32_t uh[8], ul[8];
        ldsm_x4_t(uh_b0 + bdelta, uh);     ldsm_x4_t(uh_b1 + bdelta, uh + 4);
        ldsm_x4_t(ul_b0 + bdelta, ul);     ldsm_x4_t(ul_b1 + bdelta, ul + 4);

        #pragma unroll
        for (int j = 0; j < 4; ++j) {
            const int bi = ((j >> 1) << 2) + ((j & 1) << 1);
            mma_bf16(accS[j], aeh, uh[bi], uh[bi + 1]);
            mma_bf16(accS[j], aeh, ul[bi], ul[bi + 1]);
            mma_bf16(accS[j], ael, uh[bi], uh[bi + 1]);
        }

        uint32_t vh[8], vl[8];
        ldsm_x4_t(vh_b0 + bdelta, vh);     ldsm_x4_t(vh_b1 + bdelta, vh + 4);
        ldsm_x4_t(vl_b0 + bdelta, vl);     ldsm_x4_t(vl_b1 + bdelta, vl + 4);

        #pragma unroll
        for (int j = 0; j < 4; ++j) {
            const int bi = ((j >> 1) << 2) + ((j & 1) << 1);
            mma_bf16(accD[j], aoh, vh[bi], vh[bi + 1]);
            mma_bf16(accD[j], aoh, vl[bi], vl[bi + 1]);
            mma_bf16(accD[j], aol, vh[bi], vh[bi + 1]);
        }
    }

    // epilogue: out[i] = S+D, out[127-i] = S-D
    const int g  = lane >> 2;
    const int tg = lane & 3;
    #pragma unroll
    for (int j = 0; j < 4; ++j) {
        const int p = wn + (j << 3) + (tg << 1);
        const int ia = i0 + g;
        const int ib = ia + 8;
        float2 t0 = make_float2(accS[j][0] + accD[j][0], accS[j][1] + accD[j][1]);
        float2 b0 = make_float2(accS[j][0] - accD[j][0], accS[j][1] - accD[j][1]);
        float2 t1 = make_float2(accS[j][2] + accD[j][2], accS[j][3] + accD[j][3]);
        float2 b1 = make_float2(accS[j][2] - accD[j][2], accS[j][3] - accD[j][3]);
        *(float2*)(ob + (size_t)ia * PSP + p)              = t0;
        *(float2*)(ob + (size_t)(CCH - 1 - ia) * PSP + p)  = b0;
        *(float2*)(ob + (size_t)ib * PSP + p)              = t1;
        *(float2*)(ob + (size_t)(CCH - 1 - ib) * PSP + p)  = b1;
    }
}

// ---------------------------------------------------------------------------
// Apply kernel: CTA = (p-tile, batch quad). A loaded once (cp.async) per 4
// tiles; X(t+1) LDGs issued before tile-t mma so their latency hides under it.
// ---------------------------------------------------------------------------
__global__ __launch_bounds__(NTHR, 3)
void apply_M_kernel(const float* __restrict__ x, float* __restrict__ out) {
    extern __shared__ __align__(16) unsigned char smem_raw[];
    __nv_bfloat16* sAeh = (__nv_bfloat16*)(smem_raw + 0 * 9216);
    __nv_bfloat16* sAel = (__nv_bfloat16*)(smem_raw + 1 * 9216);
    __nv_bfloat16* sAoh = (__nv_bfloat16*)(smem_raw + 2 * 9216);
    __nv_bfloat16* sAol = (__nv_bfloat16*)(smem_raw + 3 * 9216);
    __nv_bfloat16* sUh  = (__nv_bfloat16*)(smem_raw + 4 * 9216);
    __nv_bfloat16* sUl  = (__nv_bfloat16*)(smem_raw + 5 * 9216);
    __nv_bfloat16* sVh  = (__nv_bfloat16*)(smem_raw + 6 * 9216);
    __nv_bfloat16* sVl  = (__nv_bfloat16*)(smem_raw + 7 * 9216);

    const int tid = threadIdx.x;
    const int b0  = blockIdx.y * TILES;
    const int p0  = blockIdx.x * NP;

    const float* xb = x + (size_t)b0 * CCH * PSP + p0;

    const int c0 = tid >> 4;            // row group 0..15
    const int p4 = (tid & 15) << 2;     // spatial float offset

    // ---- X(0): all 8 LDG.128 issued first (MLP=8, one DRAM round trip) ----
    float4 xt[4], xm[4];
    #pragma unroll
    for (int it = 0; it < 4; ++it) {
        const int c = c0 + (it << 4);
        xt[it] = *(const float4*)(xb + (size_t)c * PSP + p4);
        xm[it] = *(const float4*)(xb + (size_t)(CCH - 1 - c) * PSP + p4);
    }

    // ---- A tiles via cp.async (L2-hot; issued after DRAM-critical X) ----
    {
        const __nv_bfloat16* srcs[4] = {g_Aehi, g_Aelo, g_Aohi, g_Aolo};
        __nv_bfloat16* dsts[4] = {sAeh, sAel, sAoh, sAol};
        #pragma unroll
        for (int a4 = 0; a4 < 4; ++a4) {
            #pragma unroll
            for (int i = 0; i < 2; ++i) {
                const int idx = tid + (i << 8);        // 0..511
                const int r   = idx >> 3;
                const int cb  = (idx & 7) << 3;
                cp_async16(smem_u32(&dsts[a4][r * PITCH + cb]),
                           srcs[a4] + (idx << 3));
            }
        }
        cp_async_commit();
    }

    fold_store(xt, xm, c0, p4, sUh, sUl, sVh, sVl);
    cp_async_wait0();
    __syncthreads();

    const int wid  = tid >> 5;
    const int lane = tid & 31;
    const int i0   = (wid & 3) << 4;
    const int wn   = (wid >> 2) << 5;

    #pragma unroll
    for (int t = 0; t < TILES; ++t) {
        // prefetch X(t+1) before this tile's mma phase
        if (t < TILES - 1) {
            const float* xn = xb + (size_t)(t + 1) * CCH * PSP;
            #pragma unroll
            for (int it = 0; it < 4; ++it) {
                const int c = c0 + (it << 4);
                xt[it] = *(const float4*)(xn + (size_t)c * PSP + p4);
                xm[it] = *(const float4*)(xn + (size_t)(CCH - 1 - c) * PSP + p4);
            }
        }

        mma_tile(sAeh, sAel, sAoh, sAol, sUh, sUl, sVh, sVl,
                 i0, wn, lane, out + (size_t)(b0 + t) * CCH * PSP + p0);
        __syncthreads();     // all warps done reading U/V before overwrite

        if (t < TILES - 1) {
            fold_store(xt, xm, c0, p4, sUh, sUl, sVh, sVl);
            __syncthreads();
        }
    }
}

// ---------------------------------------------------------------------------
extern "C" void kernel_launch(void* const* d_in, const int* in_sizes, int n_in,
                              void* d_out, int out_size) {
    const float* acts = (const float*)d_in[0];
    const float* w    = (const float*)d_in[1];
    if (n_in >= 2 && in_sizes[0] == SCOPE) {  // defensive input ordering
        const float* t = acts; acts = w; w = t;
    }
    float* out = (float*)d_out;

    cudaFuncSetAttribute(apply_M_kernel,
                         cudaFuncAttributeMaxDynamicSharedMemorySize, 8 * 9216);

    build_M_kernel<<<HCH, CCH>>>(w);
    apply_M_kernel<<<dim3(NPT, NB / TILES), NTHR, 8 * 9216>>>(acts, out);
}

// round 10
// speedup vs baseline: 1.1062x; 1.1062x over previous
#include <cuda_runtime.h>
#include <cuda_fp16.h>
#include <cstdint>

// ---------------------------------------------------------------------------
// RecurrentInhibition collapsed to y = M x (M = A^10 + 0.05*sum A^i), folded
// by centrosymmetry into two 64x64 GEMMs (S = Me u, D = Mo v).
// R9: fp16 2-term split (A = Ah+Al in fp16, B single fp16): exact to B's fp16
// quantization (~1.4e-4 global rel, gate 1e-3). Cuts ldsm + HMMA count by 33%
// vs bf16 3-term. Double-buffered U/V: one barrier per tile.
// ---------------------------------------------------------------------------

#define CCH    128
#define HCH    64
#define SCOPE  27
#define HALF   13
#define NSTEP  10
#define DECAYF 0.05f
#define PSP    3136          // 56*56
#define NB     32
#define NP     64            // spatial tile per CTA
#define NPT    49            // 3136 / 64
#define TILES  4             // batch tiles per CTA
#define PITCH  72            // fp16 row pitch: 144B = 9*16 (aligned), conflict-free
#define NTHR   256

// Folded matrices in fp16 hi/lo, row-major [i][k], i,k in 0..63
__device__ __align__(16) __half g_Aeh[HCH * HCH];
__device__ __align__(16) __half g_Ael[HCH * HCH];
__device__ __align__(16) __half g_Aoh[HCH * HCH];
__device__ __align__(16) __half g_Aol[HCH * HCH];

// ---------------------------------------------------------------------------
// Precompute: block k computes M[:,k], M[:,127-k] by iterating the recurrence
// on a unit-vector pair, folds to Me/Mo, splits fp16 hi/lo, stores [i][k].
// ---------------------------------------------------------------------------
__global__ void build_M_kernel(const float* __restrict__ w_rec) {
    __shared__ float w[SCOPE];
    __shared__ float2 ybuf[2][CCH];

    const int k = blockIdx.x;    // 0..63
    const int r = threadIdx.x;   // 0..127

    if (r < SCOPE) w[r] = w_rec[r];

    const float2 x0 = make_float2(r == k ? 1.0f : 0.0f,
                                  r == (CCH - 1 - k) ? 1.0f : 0.0f);
    ybuf[0][r] = x0;
    __syncthreads();

    int cur = 0;
    for (int it = 0; it < NSTEP; ++it) {
        float2 acc = make_float2(0.0f, 0.0f);
        #pragma unroll
        for (int t = 0; t < SCOPE; ++t) {
            int j = r + t - HALF;
            if (j >= 0 && j < CCH) {
                float2 yv = ybuf[cur][j];
                acc.x += w[t] * yv.x;
                acc.y += w[t] * yv.y;
            }
        }
        float2 yc = ybuf[cur][r];
        float2 yn;
        yn.x = (1.0f - DECAYF) * yc.x + DECAYF * (x0.x + acc.x);
        yn.y = (1.0f - DECAYF) * yc.y + DECAYF * (x0.y + acc.y);
        ybuf[cur ^ 1][r] = yn;
        __syncthreads();
        cur ^= 1;
    }

    if (r < HCH) {
        float a = ybuf[cur][r].x;          // M[r][k]
        float b = ybuf[cur][r].y;          // M[r][127-k]
        float me = 0.5f * (a + b);
        float mo = 0.5f * (a - b);
        __half mh = __float2half_rn(me);
        __half ml = __float2half_rn(me - __half2float(mh));
        __half oh = __float2half_rn(mo);
        __half ol = __float2half_rn(mo - __half2float(oh));
        g_Aeh[r * HCH + k] = mh;
        g_Ael[r * HCH + k] = ml;
        g_Aoh[r * HCH + k] = oh;
        g_Aol[r * HCH + k] = ol;
    }
}

// ---------------------------------------------------------------------------
// PTX helpers (sm_100-safe: mma.sync / ldmatrix / cp.async only)
// ---------------------------------------------------------------------------
__device__ __forceinline__ uint32_t smem_u32(const void* p) {
    uint32_t a;
    asm("{ .reg .u64 t; cvta.to.shared.u64 t, %1; cvt.u32.u64 %0, t; }"
        : "=r"(a) : "l"(p));
    return a;
}
__device__ __forceinline__ void cp_async16(uint32_t dst, const void* src) {
    asm volatile("cp.async.cg.shared.global [%0], [%1], 16;"
                 :: "r"(dst), "l"(src));
}
__device__ __forceinline__ void cp_async_commit() {
    asm volatile("cp.async.commit_group;");
}
__device__ __forceinline__ void cp_async_wait0() {
    asm volatile("cp.async.wait_group 0;");
}
__device__ __forceinline__ void ldsm_x4(uint32_t addr, uint32_t r[4]) {
    asm volatile("ldmatrix.sync.aligned.m8n8.x4.shared.b16 {%0,%1,%2,%3}, [%4];"
                 : "=r"(r[0]), "=r"(r[1]), "=r"(r[2]), "=r"(r[3]) : "r"(addr));
}
__device__ __forceinline__ void ldsm_x4_t(uint32_t addr, uint32_t r[4]) {
    asm volatile("ldmatrix.sync.aligned.m8n8.x4.trans.shared.b16 {%0,%1,%2,%3}, [%4];"
                 : "=r"(r[0]), "=r"(r[1]), "=r"(r[2]), "=r"(r[3]) : "r"(addr));
}
__device__ __forceinline__ void mma_fp16(float d[4], const uint32_t a[4],
                                         uint32_t b0, uint32_t b1) {
    asm volatile(
        "mma.sync.aligned.m16n8k16.row.col.f32.f16.f16.f32 "
        "{%0,%1,%2,%3}, {%4,%5,%6,%7}, {%8,%9}, {%0,%1,%2,%3};"
        : "+f"(d[0]), "+f"(d[1]), "+f"(d[2]), "+f"(d[3])
        : "r"(a[0]), "r"(a[1]), "r"(a[2]), "r"(a[3]), "r"(b0), "r"(b1));
}
__device__ __forceinline__ uint32_t pack_h2(float a, float b) {
    __half2 h = __floats2half2_rn(a, b);   // .x = a (low half)
    return *reinterpret_cast<uint32_t*>(&h);
}

// ---------------------------------------------------------------------------
// Fold registers (xt = x rows c, xm = mirror rows 127-c) into fp16 smem.
// ---------------------------------------------------------------------------
__device__ __forceinline__ void fold_store(const float4 xt[4], const float4 xm[4],
                                           int c0, int p4,
                                           __half* sU, __half* sV) {
    #pragma unroll
    for (int it = 0; it < 4; ++it) {
        const int c = c0 + (it << 4);
        uint2 wu = make_uint2(pack_h2(xt[it].x + xm[it].x, xt[it].y + xm[it].y),
                              pack_h2(xt[it].z + xm[it].z, xt[it].w + xm[it].w));
        uint2 wv = make_uint2(pack_h2(xt[it].x - xm[it].x, xt[it].y - xm[it].y),
                              pack_h2(xt[it].z - xm[it].z, xt[it].w - xm[it].w));
        const int off = c * PITCH + p4;
        *(uint2*)&sU[off] = wu;
        *(uint2*)&sV[off] = wv;
    }
}

// ---------------------------------------------------------------------------
// MMA phase + epilogue for one tile. Per kk: 4 A-ldsm + 4 B-ldsm, 16 HMMA.
// S = (Aeh + Ael) * U = Me * fp16(u);  D = Mo * fp16(v).
// ---------------------------------------------------------------------------
__device__ __forceinline__ void mma_tile(
    const __half* sAeh, const __half* sAel,
    const __half* sAoh, const __half* sAol,
    const __half* sU,   const __half* sV,
    int i0, int wn, int lane, float* ob /* out + b*CCH*PSP + p0 */) {

    const int lr = lane & 15;
    const int lc = (lane >> 4) << 3;

    const uint32_t aeh_b = smem_u32(&sAeh[(i0 + lr) * PITCH + lc]);
    const uint32_t ael_b = smem_u32(&sAel[(i0 + lr) * PITCH + lc]);
    const uint32_t aoh_b = smem_u32(&sAoh[(i0 + lr) * PITCH + lc]);
    const uint32_t aol_b = smem_u32(&sAol[(i0 + lr) * PITCH + lc]);
    const uint32_t u_b0  = smem_u32(&sU[lr * PITCH + wn + lc]);
    const uint32_t u_b1  = smem_u32(&sU[lr * PITCH + wn + 16 + lc]);
    const uint32_t v_b0  = smem_u32(&sV[lr * PITCH + wn + lc]);
    const uint32_t v_b1  = smem_u32(&sV[lr * PITCH + wn + 16 + lc]);

    float accS[4][4], accD[4][4];
    #pragma unroll
    for (int j = 0; j < 4; ++j)
        #pragma unroll
        for (int e = 0; e < 4; ++e) { accS[j][e] = 0.0f; accD[j][e] = 0.0f; }

    #pragma unroll
    for (int kk = 0; kk < 4; ++kk) {
        const uint32_t adelta = kk * 32;                 // 16 fp16 along k
        const uint32_t bdelta = kk * 16 * PITCH * 2;     // 16 k-rows

        uint32_t aeh[4], ael[4], aoh[4], aol[4];
        ldsm_x4(aeh_b + adelta, aeh);
        ldsm_x4(ael_b + adelta, ael);
        ldsm_x4(aoh_b + adelta, aoh);
        ldsm_x4(aol_b + adelta, aol);

        uint32_t uu[8], vv[8];
        ldsm_x4_t(u_b0 + bdelta, uu);     ldsm_x4_t(u_b1 + bdelta, uu + 4);
        ldsm_x4_t(v_b0 + bdelta, vv);     ldsm_x4_t(v_b1 + bdelta, vv + 4);

        #pragma unroll
        for (int j = 0; j < 4; ++j) {
            const int bi = ((j >> 1) << 2) + ((j & 1) << 1);
            mma_fp16(accS[j], aeh, uu[bi], uu[bi + 1]);
            mma_fp16(accS[j], ael, uu[bi], uu[bi + 1]);
            mma_fp16(accD[j], aoh, vv[bi], vv[bi + 1]);
            mma_fp16(accD[j], aol, vv[bi], vv[bi + 1]);
        }
    }

    // epilogue: out[i] = S+D, out[127-i] = S-D
    const int g  = lane >> 2;
    const int tg = lane & 3;
    #pragma unroll
    for (int j = 0; j < 4; ++j) {
        const int p = wn + (j << 3) + (tg << 1);
        const int ia = i0 + g;
        const int ib = ia + 8;
        float2 t0 = make_float2(accS[j][0] + accD[j][0], accS[j][1] + accD[j][1]);
        float2 b0 = make_float2(accS[j][0] - accD[j][0], accS[j][1] - accD[j][1]);
        float2 t1 = make_float2(accS[j][2] + accD[j][2], accS[j][3] + accD[j][3]);
        float2 b1 = make_float2(accS[j][2] - accD[j][2], accS[j][3] - accD[j][3]);
        *(float2*)(ob + (size_t)ia * PSP + p)              = t0;
        *(float2*)(ob + (size_t)(CCH - 1 - ia) * PSP + p)  = b0;
        *(float2*)(ob + (size_t)ib * PSP + p)              = t1;
        *(float2*)(ob + (size_t)(CCH - 1 - ib) * PSP + p)  = b1;
    }
}

// ---------------------------------------------------------------------------
// Apply kernel: CTA = (p-tile, batch quad). A loaded once per 4 tiles via
// cp.async. U/V double-buffered: per tile, mma(buf t) then fold(buf t+1) with
// a single barrier — fold overlaps other warps' mma tail.
// ---------------------------------------------------------------------------
__global__ __launch_bounds__(NTHR, 3)
void apply_M_kernel(const float* __restrict__ x, float* __restrict__ out) {
    extern __shared__ __align__(16) unsigned char smem_raw[];
    __half* sAeh = (__half*)(smem_raw + 0 * 9216);
    __half* sAel = (__half*)(smem_raw + 1 * 9216);
    __half* sAoh = (__half*)(smem_raw + 2 * 9216);
    __half* sAol = (__half*)(smem_raw + 3 * 9216);
    __half* sU[2] = {(__half*)(smem_raw + 4 * 9216), (__half*)(smem_raw + 5 * 9216)};
    __half* sV[2] = {(__half*)(smem_raw + 6 * 9216), (__half*)(smem_raw + 7 * 9216)};

    const int tid = threadIdx.x;
    const int b0  = blockIdx.y * TILES;
    const int p0  = blockIdx.x * NP;

    const float* xb = x + (size_t)b0 * CCH * PSP + p0;

    const int c0 = tid >> 4;            // row group 0..15
    const int p4 = (tid & 15) << 2;     // spatial float offset

    // ---- X(0): all 8 LDG.128 issued first (MLP=8, one DRAM round trip) ----
    float4 xt[4], xm[4];
    #pragma unroll
    for (int it = 0; it < 4; ++it) {
        const int c = c0 + (it << 4);
        xt[it] = *(const float4*)(xb + (size_t)c * PSP + p4);
        xm[it] = *(const float4*)(xb + (size_t)(CCH - 1 - c) * PSP + p4);
    }

    // ---- A tiles via cp.async (L2-hot; issued after DRAM-critical X) ----
    {
        const __half* srcs[4] = {g_Aeh, g_Ael, g_Aoh, g_Aol};
        __half* dsts[4] = {sAeh, sAel, sAoh, sAol};
        #pragma unroll
        for (int a4 = 0; a4 < 4; ++a4) {
            #pragma unroll
            for (int i = 0; i < 2; ++i) {
                const int idx = tid + (i << 8);        // 0..511
                const int r   = idx >> 3;
                const int cb  = (idx & 7) << 3;
                cp_async16(smem_u32(&dsts[a4][r * PITCH + cb]),
                           srcs[a4] + (idx << 3));
            }
        }
        cp_async_commit();
    }

    fold_store(xt, xm, c0, p4, sU[0], sV[0]);
    cp_async_wait0();
    __syncthreads();

    const int wid  = tid >> 5;
    const int lane = tid & 31;
    const int i0   = (wid & 3) << 4;
    const int wn   = (wid >> 2) << 5;

    #pragma unroll
    for (int t = 0; t < TILES; ++t) {
        // prefetch X(t+1) before this tile's mma phase (hides DRAM latency)
        if (t < TILES - 1) {
            const float* xn = xb + (size_t)(t + 1) * CCH * PSP;
            #pragma unroll
            for (int it = 0; it < 4; ++it) {
                const int c = c0 + (it << 4);
                xt[it] = *(const float4*)(xn + (size_t)c * PSP + p4);
                xm[it] = *(const float4*)(xn + (size_t)(CCH - 1 - c) * PSP + p4);
            }
        }

        mma_tile(sAeh, sAel, sAoh, sAol, sU[t & 1], sV[t & 1],
                 i0, wn, lane, out + (size_t)(b0 + t) * CCH * PSP + p0);

        if (t < TILES - 1) {
            // write the *other* buffer: last read at iteration t-1 whose
            // trailing __syncthreads() already fenced it — no pre-sync needed
            fold_store(xt, xm, c0, p4, sU[(t + 1) & 1], sV[(t + 1) & 1]);
            __syncthreads();
        }
    }
}

// ---------------------------------------------------------------------------
extern "C" void kernel_launch(void* const* d_in, const int* in_sizes, int n_in,
                              void* d_out, int out_size) {
    const float* acts = (const float*)d_in[0];
    const float* w    = (const float*)d_in[1];
    if (n_in >= 2 && in_sizes[0] == SCOPE) {  // defensive input ordering
        const float* t = acts; acts = w; w = t;
    }
    float* out = (float*)d_out;

    cudaFuncSetAttribute(apply_M_kernel,
                         cudaFuncAttributeMaxDynamicSharedMemorySize, 8 * 9216);

    build_M_kernel<<<HCH, CCH>>>(w);
    apply_M_kernel<<<dim3(NPT, NB / TILES), NTHR, 8 * 9216>>>(acts, out);
}

// round 12
// speedup vs baseline: 1.2300x; 1.1120x over previous
#include <cuda_runtime.h>
#include <cuda_fp16.h>
#include <cstdint>

// ---------------------------------------------------------------------------
// RecurrentInhibition collapsed to y = M x (M = A^10 + 0.05*sum A^i), folded
// by centrosymmetry into two 64x64 GEMMs (S = Me u, D = Mo v).
// R11: single-term fp16 (A and B both single fp16; measured B-only error was
// 2.07e-4, predicted combined ~2.5e-4 vs 1e-3 gate). Halves HMMA, cuts ldsm
// 25% and A-traffic 50% vs R10. Double-buffered U/V, one barrier per tile.
// ---------------------------------------------------------------------------

#define CCH    128
#define HCH    64
#define SCOPE  27
#define HALF   13
#define NSTEP  10
#define DECAYF 0.05f
#define PSP    3136          // 56*56
#define NB     32
#define NP     64            // spatial tile per CTA
#define NPT    49            // 3136 / 64
#define TILES  4             // batch tiles per CTA
#define PITCH  72            // fp16 row pitch: 144B = 9*16 (aligned), conflict-free
#define NTHR   256

// Folded matrices in fp16, row-major [i][k], i,k in 0..63
__device__ __align__(16) __half g_Ae[HCH * HCH];
__device__ __align__(16) __half g_Ao[HCH * HCH];

// ---------------------------------------------------------------------------
// Precompute: block k computes M[:,k], M[:,127-k] by iterating the recurrence
// on a unit-vector pair, folds to Me/Mo, rounds to fp16, stores [i][k].
// ---------------------------------------------------------------------------
__global__ void build_M_kernel(const float* __restrict__ w_rec) {
    __shared__ float w[SCOPE];
    __shared__ float2 ybuf[2][CCH];

    const int k = blockIdx.x;    // 0..63
    const int r = threadIdx.x;   // 0..127

    if (r < SCOPE) w[r] = w_rec[r];

    const float2 x0 = make_float2(r == k ? 1.0f : 0.0f,
                                  r == (CCH - 1 - k) ? 1.0f : 0.0f);
    ybuf[0][r] = x0;
    __syncthreads();

    int cur = 0;
    for (int it = 0; it < NSTEP; ++it) {
        float2 acc = make_float2(0.0f, 0.0f);
        #pragma unroll
        for (int t = 0; t < SCOPE; ++t) {
            int j = r + t - HALF;
            if (j >= 0 && j < CCH) {
                float2 yv = ybuf[cur][j];
                acc.x += w[t] * yv.x;
                acc.y += w[t] * yv.y;
            }
        }
        float2 yc = ybuf[cur][r];
        float2 yn;
        yn.x = (1.0f - DECAYF) * yc.x + DECAYF * (x0.x + acc.x);
        yn.y = (1.0f - DECAYF) * yc.y + DECAYF * (x0.y + acc.y);
        ybuf[cur ^ 1][r] = yn;
        __syncthreads();
        cur ^= 1;
    }

    if (r < HCH) {
        float a = ybuf[cur][r].x;          // M[r][k]
        float b = ybuf[cur][r].y;          // M[r][127-k]
        g_Ae[r * HCH + k] = __float2half_rn(0.5f * (a + b));
        g_Ao[r * HCH + k] = __float2half_rn(0.5f * (a - b));
    }
}

// ---------------------------------------------------------------------------
// PTX helpers (sm_100-safe: mma.sync / ldmatrix / cp.async only)
// ---------------------------------------------------------------------------
__device__ __forceinline__ uint32_t smem_u32(const void* p) {
    uint32_t a;
    asm("{ .reg .u64 t; cvta.to.shared.u64 t, %1; cvt.u32.u64 %0, t; }"
        : "=r"(a) : "l"(p));
    return a;
}
__device__ __forceinline__ void cp_async16(uint32_t dst, const void* src) {
    asm volatile("cp.async.cg.shared.global [%0], [%1], 16;"
                 :: "r"(dst), "l"(src));
}
__device__ __forceinline__ void cp_async_commit() {
    asm volatile("cp.async.commit_group;");
}
__device__ __forceinline__ void cp_async_wait0() {
    asm volatile("cp.async.wait_group 0;");
}
__device__ __forceinline__ void ldsm_x4(uint32_t addr, uint32_t r[4]) {
    asm volatile("ldmatrix.sync.aligned.m8n8.x4.shared.b16 {%0,%1,%2,%3}, [%4];"
                 : "=r"(r[0]), "=r"(r[1]), "=r"(r[2]), "=r"(r[3]) : "r"(addr));
}
__device__ __forceinline__ void ldsm_x4_t(uint32_t addr, uint32_t r[4]) {
    asm volatile("ldmatrix.sync.aligned.m8n8.x4.trans.shared.b16 {%0,%1,%2,%3}, [%4];"
                 : "=r"(r[0]), "=r"(r[1]), "=r"(r[2]), "=r"(r[3]) : "r"(addr));
}
__device__ __forceinline__ void mma_fp16(float d[4], const uint32_t a[4],
                                         uint32_t b0, uint32_t b1) {
    asm volatile(
        "mma.sync.aligned.m16n8k16.row.col.f32.f16.f16.f32 "
        "{%0,%1,%2,%3}, {%4,%5,%6,%7}, {%8,%9}, {%0,%1,%2,%3};"
        : "+f"(d[0]), "+f"(d[1]), "+f"(d[2]), "+f"(d[3])
        : "r"(a[0]), "r"(a[1]), "r"(a[2]), "r"(a[3]), "r"(b0), "r"(b1));
}
__device__ __forceinline__ uint32_t pack_h2(float a, float b) {
    __half2 h = __floats2half2_rn(a, b);   // .x = a (low half)
    return *reinterpret_cast<uint32_t*>(&h);
}

// ---------------------------------------------------------------------------
// Fold registers (xt = x rows c, xm = mirror rows 127-c) into fp16 smem.
// ---------------------------------------------------------------------------
__device__ __forceinline__ void fold_store(const float4 xt[4], const float4 xm[4],
                                           int c0, int p4,
                                           __half* sU, __half* sV) {
    #pragma unroll
    for (int it = 0; it < 4; ++it) {
        const int c = c0 + (it << 4);
        uint2 wu = make_uint2(pack_h2(xt[it].x + xm[it].x, xt[it].y + xm[it].y),
                              pack_h2(xt[it].z + xm[it].z, xt[it].w + xm[it].w));
        uint2 wv = make_uint2(pack_h2(xt[it].x - xm[it].x, xt[it].y - xm[it].y),
                              pack_h2(xt[it].z - xm[it].z, xt[it].w - xm[it].w));
        const int off = c * PITCH + p4;
        *(uint2*)&sU[off] = wu;
        *(uint2*)&sV[off] = wv;
    }
}

// ---------------------------------------------------------------------------
// MMA phase + epilogue for one tile. Per kk: 2 A-ldsm + 4 B-ldsm, 8 HMMA.
// ---------------------------------------------------------------------------
__device__ __forceinline__ void mma_tile(
    const __half* sAe, const __half* sAo,
    const __half* sU,  const __half* sV,
    int i0, int wn, int lane, float* ob /* out + b*CCH*PSP + p0 */) {

    const int lr = lane & 15;
    const int lc = (lane >> 4) << 3;

    const uint32_t ae_b = smem_u32(&sAe[(i0 + lr) * PITCH + lc]);
    const uint32_t ao_b = smem_u32(&sAo[(i0 + lr) * PITCH + lc]);
    const uint32_t u_b0 = smem_u32(&sU[lr * PITCH + wn + lc]);
    const uint32_t u_b1 = smem_u32(&sU[lr * PITCH + wn + 16 + lc]);
    const uint32_t v_b0 = smem_u32(&sV[lr * PITCH + wn + lc]);
    const uint32_t v_b1 = smem_u32(&sV[lr * PITCH + wn + 16 + lc]);

    float accS[4][4], accD[4][4];
    #pragma unroll
    for (int j = 0; j < 4; ++j)
        #pragma unroll
        for (int e = 0; e < 4; ++e) { accS[j][e] = 0.0f; accD[j][e] = 0.0f; }

    #pragma unroll
    for (int kk = 0; kk < 4; ++kk) {
        const uint32_t adelta = kk * 32;                 // 16 fp16 along k
        const uint32_t bdelta = kk * 16 * PITCH * 2;     // 16 k-rows

        uint32_t ae[4], ao[4];
        ldsm_x4(ae_b + adelta, ae);
        ldsm_x4(ao_b + adelta, ao);

        uint32_t uu[8], vv[8];
        ldsm_x4_t(u_b0 + bdelta, uu);     ldsm_x4_t(u_b1 + bdelta, uu + 4);
        ldsm_x4_t(v_b0 + bdelta, vv);     ldsm_x4_t(v_b1 + bdelta, vv + 4);

        #pragma unroll
        for (int j = 0; j < 4; ++j) {
            const int bi = ((j >> 1) << 2) + ((j & 1) << 1);
            mma_fp16(accS[j], ae, uu[bi], uu[bi + 1]);
            mma_fp16(accD[j], ao, vv[bi], vv[bi + 1]);
        }
    }

    // epilogue: out[i] = S+D, out[127-i] = S-D
    const int g  = lane >> 2;
    const int tg = lane & 3;
    #pragma unroll
    for (int j = 0; j < 4; ++j) {
        const int p = wn + (j << 3) + (tg << 1);
        const int ia = i0 + g;
        const int ib = ia + 8;
        float2 t0 = make_float2(accS[j][0] + accD[j][0], accS[j][1] + accD[j][1]);
        float2 b0 = make_float2(accS[j][0] - accD[j][0], accS[j][1] - accD[j][1]);
        float2 t1 = make_float2(accS[j][2] + accD[j][2], accS[j][3] + accD[j][3]);
        float2 b1 = make_float2(accS[j][2] - accD[j][2], accS[j][3] - accD[j][3]);
        *(float2*)(ob + (size_t)ia * PSP + p)              = t0;
        *(float2*)(ob + (size_t)(CCH - 1 - ia) * PSP + p)  = b0;
        *(float2*)(ob + (size_t)ib * PSP + p)              = t1;
        *(float2*)(ob + (size_t)(CCH - 1 - ib) * PSP + p)  = b1;
    }
}

// ---------------------------------------------------------------------------
// Apply kernel: CTA = (p-tile, batch quad). A loaded once per 4 tiles via
// cp.async. U/V double-buffered: one barrier per tile; fold(t+1) overlaps
// other warps' mma(t) tail.
// ---------------------------------------------------------------------------
__global__ __launch_bounds__(NTHR, 3)
void apply_M_kernel(const float* __restrict__ x, float* __restrict__ out) {
    extern __shared__ __align__(16) unsigned char smem_raw[];
    __half* sAe = (__half*)(smem_raw + 0 * 9216);
    __half* sAo = (__half*)(smem_raw + 1 * 9216);
    __half* sU[2] = {(__half*)(smem_raw + 2 * 9216), (__half*)(smem_raw + 3 * 9216)};
    __half* sV[2] = {(__half*)(smem_raw + 4 * 9216), (__half*)(smem_raw + 5 * 9216)};

    const int tid = threadIdx.x;
    const int b0  = blockIdx.y * TILES;
    const int p0  = blockIdx.x * NP;

    const float* xb = x + (size_t)b0 * CCH * PSP + p0;

    const int c0 = tid >> 4;            // row group 0..15
    const int p4 = (tid & 15) << 2;     // spatial float offset

    // ---- X(0): all 8 LDG.128 issued first (MLP=8, one DRAM round trip) ----
    float4 xt[4], xm[4];
    #pragma unroll
    for (int it = 0; it < 4; ++it) {
        const int c = c0 + (it << 4);
        xt[it] = *(const float4*)(xb + (size_t)c * PSP + p4);
        xm[it] = *(const float4*)(xb + (size_t)(CCH - 1 - c) * PSP + p4);
    }

    // ---- A tiles via cp.async (L2-hot; issued after DRAM-critical X) ----
    {
        const __half* srcs[2] = {g_Ae, g_Ao};
        __half* dsts[2] = {sAe, sAo};
        #pragma unroll
        for (int a2 = 0; a2 < 2; ++a2) {
            #pragma unroll
            for (int i = 0; i < 2; ++i) {
                const int idx = tid + (i << 8);        // 0..511
                const int r   = idx >> 3;
                const int cb  = (idx & 7) << 3;
                cp_async16(smem_u32(&dsts[a2][r * PITCH + cb]),
                           srcs[a2] + (idx << 3));
            }
        }
        cp_async_commit();
    }

    fold_store(xt, xm, c0, p4, sU[0], sV[0]);
    cp_async_wait0();
    __syncthreads();

    const int wid  = tid >> 5;
    const int lane = tid & 31;
    const int i0   = (wid & 3) << 4;
    const int wn   = (wid >> 2) << 5;

    #pragma unroll
    for (int t = 0; t < TILES; ++t) {
        // prefetch X(t+1) before this tile's mma phase (hides DRAM latency)
        if (t < TILES - 1) {
            const float* xn = xb + (size_t)(t + 1) * CCH * PSP;
            #pragma unroll
            for (int it = 0; it < 4; ++it) {
                const int c = c0 + (it << 4);
                xt[it] = *(const float4*)(xn + (size_t)c * PSP + p4);
                xm[it] = *(const float4*)(xn + (size_t)(CCH - 1 - c) * PSP + p4);
            }
        }

        mma_tile(sAe, sAo, sU[t & 1], sV[t & 1],
                 i0, wn, lane, out + (size_t)(b0 + t) * CCH * PSP + p0);

        if (t < TILES - 1) {
            // write the *other* buffer: last read at iteration t-1 whose
            // trailing __syncthreads() already fenced it — no pre-sync needed
            fold_store(xt, xm, c0, p4, sU[(t + 1) & 1], sV[(t + 1) & 1]);
            __syncthreads();
        }
    }
}

// ---------------------------------------------------------------------------
extern "C" void kernel_launch(void* const* d_in, const int* in_sizes, int n_in,
                              void* d_out, int out_size) {
    const float* acts = (const float*)d_in[0];
    const float* w    = (const float*)d_in[1];
    if (n_in >= 2 && in_sizes[0] == SCOPE) {  // defensive input ordering
        const float* t = acts; acts = w; w = t;
    }
    float* out = (float*)d_out;

    cudaFuncSetAttribute(apply_M_kernel,
                         cudaFuncAttributeMaxDynamicSharedMemorySize, 6 * 9216);

    build_M_kernel<<<HCH, CCH>>>(w);
    apply_M_kernel<<<dim3(NPT, NB / TILES), NTHR, 6 * 9216>>>(acts, out);
}